// round 8
// baseline (speedup 1.0000x reference)
#include <cuda_runtime.h>
#include <math.h>

#define F      128
#define HEADS  4
#define NMAX   50000
#define GMAX   64
#define EMAX   860000
#define XPAD   68

// ---------------- device scratch ----------------
__device__ __align__(16) float g_h   [NMAX * F];
__device__ __align__(16) float g_buf [NMAX * F];
__device__ __align__(16) float g_as  [NMAX * HEADS];
__device__ __align__(16) float g_ad  [NMAX * HEADS];
__device__ __align__(16) float g_psum[GMAX * F];
__device__ __align__(16) float g_pmax[GMAX * F];
__device__             float g_cnt [GMAX];
__device__ __align__(16) int  g_deg [NMAX];          // zero-init; scan_k restores zeros
__device__             int   g_rowptr[NMAX + 1];
__device__             int   g_wpos[NMAX];
__device__             int   g_csrc[EMAX];

// ---------------- helpers ----------------
__device__ __forceinline__ void atomicMaxFloat(float* addr, float value) {
    if (value >= 0.f) atomicMax((int*)addr, __float_as_int(value));
    else              atomicMin((unsigned int*)addr, __float_as_uint(value));
}

__device__ __forceinline__ void redAddV4(float* p, float a, float b, float c, float d) {
    asm volatile("red.global.add.v4.f32 [%0], {%1,%2,%3,%4};"
                 :: "l"(p), "f"(a), "f"(b), "f"(c), "f"(d) : "memory");
}

// ---------------- GEMM + fused alpha (+ optional edge count) ----------------
__global__ void gemm_k(const float* __restrict__ X, const float* __restrict__ W,
                       float* __restrict__ O,
                       const float* __restrict__ asr, const float* __restrict__ adt,
                       int N, const int* __restrict__ ei, int E, int do_count) {
    extern __shared__ float sm[];
    float* xs = sm;            // [128][XPAD]

    const int tid  = threadIdx.x;
    const int row0 = blockIdx.x * 64;

    if (do_count) {
        int stride = gridDim.x * blockDim.x;
        int Et = E + N;
        for (int i = blockIdx.x * blockDim.x + tid; i < Et; i += stride) {
            int dst = (i < E) ? __ldg(&ei[E + i]) : (i - E);
            atomicAdd(&g_deg[dst], 1);
        }
    }

    const float4* X4 = (const float4*)X;
#pragma unroll
    for (int i = 0; i < 8; i++) {
        int idx = tid + i * 256;
        int r = idx >> 5, kq = idx & 31;
        float4 v = make_float4(0.f, 0.f, 0.f, 0.f);
        int gr = row0 + r;
        if (gr < N) v = X4[gr * 32 + kq];
        xs[(4 * kq + 0) * XPAD + r] = v.x;
        xs[(4 * kq + 1) * XPAD + r] = v.y;
        xs[(4 * kq + 2) * XPAD + r] = v.z;
        xs[(4 * kq + 3) * XPAD + r] = v.w;
    }
    __syncthreads();

    const int ty = tid >> 4, tx = tid & 15;
    float acc[4][8];
#pragma unroll
    for (int i = 0; i < 4; i++)
#pragma unroll
        for (int j = 0; j < 8; j++) acc[i][j] = 0.f;

#pragma unroll 4
    for (int k = 0; k < F; k++) {
        float4 x4 = *(const float4*)&xs[k * XPAD + ty * 4];
        float xr[4] = {x4.x, x4.y, x4.z, x4.w};
        float4 w0 = __ldg((const float4*)&W[k * F + tx * 8]);
        float4 w1 = __ldg((const float4*)&W[k * F + tx * 8 + 4]);
        float wr[8] = {w0.x, w0.y, w0.z, w0.w, w1.x, w1.y, w1.z, w1.w};
#pragma unroll
        for (int i = 0; i < 4; i++)
#pragma unroll
            for (int j = 0; j < 8; j++) acc[i][j] = fmaf(xr[i], wr[j], acc[i][j]);
    }

    float4 a0 = *(const float4*)&asr[tx * 8];
    float4 a1 = *(const float4*)&asr[tx * 8 + 4];
    float4 d0 = *(const float4*)&adt[tx * 8];
    float4 d1 = *(const float4*)&adt[tx * 8 + 4];
    float av[8] = {a0.x, a0.y, a0.z, a0.w, a1.x, a1.y, a1.z, a1.w};
    float dv[8] = {d0.x, d0.y, d0.z, d0.w, d1.x, d1.y, d1.z, d1.w};

    const int lane = tid & 31;
    const int head = (lane >> 2) & 3;

#pragma unroll
    for (int i = 0; i < 4; i++) {
        int gr = row0 + ty * 4 + i;
        float ps = 0.f, pd = 0.f;
#pragma unroll
        for (int j = 0; j < 8; j++) {
            ps = fmaf(acc[i][j], av[j], ps);
            pd = fmaf(acc[i][j], dv[j], pd);
        }
        ps += __shfl_down_sync(0xffffffffu, ps, 1, 4);
        ps += __shfl_down_sync(0xffffffffu, ps, 2, 4);
        pd += __shfl_down_sync(0xffffffffu, pd, 1, 4);
        pd += __shfl_down_sync(0xffffffffu, pd, 2, 4);
        if (gr < N) {
            if ((lane & 3) == 0) {
                g_as[gr * 4 + head] = ps;
                g_ad[gr * 4 + head] = pd;
            }
            *(float4*)&O[gr * F + tx * 8]     = make_float4(acc[i][0], acc[i][1], acc[i][2], acc[i][3]);
            *(float4*)&O[gr * F + tx * 8 + 4] = make_float4(acc[i][4], acc[i][5], acc[i][6], acc[i][7]);
        }
    }
}

// ---------------- single-block scan, 4 items/thread; zeros g_deg ----------------
__global__ void scan_k(int N) {
    __shared__ int warpsum[32];
    __shared__ int carry_s;
    int tid = threadIdx.x, lane = tid & 31, wid = tid >> 5;
    if (tid == 0) carry_s = 0;
    __syncthreads();
    for (int base = 0; base < N; base += 4096) {
        int i = base + tid * 4;
        int4 v = make_int4(0, 0, 0, 0);
        bool full = (i + 3 < N);
        if (full) v = *(const int4*)&g_deg[i];
        else if (i < N) {
            v.x = g_deg[i];
            if (i + 1 < N) v.y = g_deg[i + 1];
            if (i + 2 < N) v.z = g_deg[i + 2];
        }
        int t1 = v.x + v.y, t2 = t1 + v.z, t3 = t2 + v.w;
        int x = t3;
#pragma unroll
        for (int o = 1; o < 32; o <<= 1) {
            int t = __shfl_up_sync(0xffffffffu, x, o);
            if (lane >= o) x += t;
        }
        if (lane == 31) warpsum[wid] = x;
        __syncthreads();
        if (wid == 0) {
            int s = warpsum[lane];
#pragma unroll
            for (int o = 1; o < 32; o <<= 1) {
                int t = __shfl_up_sync(0xffffffffu, s, o);
                if (lane >= o) s += t;
            }
            warpsum[lane] = s;
        }
        __syncthreads();
        int c    = carry_s;
        int pref = (wid > 0) ? warpsum[wid - 1] : 0;
        int e0 = c + pref + (x - t3);
        if (full) {
            g_rowptr[i] = e0;       g_wpos[i]     = e0;
            g_rowptr[i+1] = e0+v.x; g_wpos[i+1]   = e0+v.x;
            g_rowptr[i+2] = e0+t1;  g_wpos[i+2]   = e0+t1;
            g_rowptr[i+3] = e0+t2;  g_wpos[i+3]   = e0+t2;
            *(int4*)&g_deg[i] = make_int4(0, 0, 0, 0);
        } else if (i < N) {
            g_rowptr[i] = e0; g_wpos[i] = e0; g_deg[i] = 0;
            if (i+1 < N) { g_rowptr[i+1] = e0+v.x; g_wpos[i+1] = e0+v.x; g_deg[i+1] = 0; }
            if (i+2 < N) { g_rowptr[i+2] = e0+t1;  g_wpos[i+2] = e0+t1;  g_deg[i+2] = 0; }
        }
        __syncthreads();
        if (tid == 1023) carry_s = c + pref + x;
        __syncthreads();
    }
    if (threadIdx.x == 0) g_rowptr[N] = carry_s;
}

__global__ void scatter_k(const int* __restrict__ ei, int E, int N) {
    int i = blockIdx.x * blockDim.x + threadIdx.x;
    int Et = E + N;
    if (i >= Et) return;
    int src, dst;
    if (i < E) { src = ei[i]; dst = ei[E + i]; }
    else       { src = dst = i - E; }
    int pos = atomicAdd(&g_wpos[dst], 1);
    g_csrc[pos] = src;
}

// ---------------- fused softmax+aggregation, warp per dst, 4 edge slots ----------------
// lane = slot*8 + fl; slot handles edges i0+slot, i0+slot+4, ...
// lane fl covers features [fl*16, fl*16+16) -> single head (fl>>1).
__global__ void __launch_bounds__(256)
aggr_k(const float* __restrict__ Hm,
       float* __restrict__ O,
       const float* __restrict__ bias,
       const int* __restrict__ batch,
       int N, int do_elu, int do_pool) {
    int d    = (blockIdx.x * blockDim.x + threadIdx.x) >> 5;
    int lane = threadIdx.x & 31;
    if (d >= N) return;
    int slot = lane >> 3;
    int fl   = lane & 7;
    int head = fl >> 1;

    float adh = g_ad[d * 4 + head];
    int i0 = g_rowptr[d];
    int i1 = g_rowptr[d + 1];

    float acc[16];
#pragma unroll
    for (int q = 0; q < 16; q++) acc[q] = 0.f;
    float sw = 0.f;

    for (int i = i0 + slot; i < i1; i += 4) {
        int s = __ldg(&g_csrc[i]);
        float a = __ldg(&g_as[s * 4 + head]);
        const float4* hp = (const float4*)(Hm + s * F + fl * 16);
        float4 h0 = hp[0], h1 = hp[1], h2 = hp[2], h3 = hp[3];
        float e = a + adh;
        e = e > 0.f ? e : 0.2f * e;
        float w = __expf(e);
        sw += w;
        acc[0]  = fmaf(w, h0.x, acc[0]);  acc[1]  = fmaf(w, h0.y, acc[1]);
        acc[2]  = fmaf(w, h0.z, acc[2]);  acc[3]  = fmaf(w, h0.w, acc[3]);
        acc[4]  = fmaf(w, h1.x, acc[4]);  acc[5]  = fmaf(w, h1.y, acc[5]);
        acc[6]  = fmaf(w, h1.z, acc[6]);  acc[7]  = fmaf(w, h1.w, acc[7]);
        acc[8]  = fmaf(w, h2.x, acc[8]);  acc[9]  = fmaf(w, h2.y, acc[9]);
        acc[10] = fmaf(w, h2.z, acc[10]); acc[11] = fmaf(w, h2.w, acc[11]);
        acc[12] = fmaf(w, h3.x, acc[12]); acc[13] = fmaf(w, h3.y, acc[13]);
        acc[14] = fmaf(w, h3.z, acc[14]); acc[15] = fmaf(w, h3.w, acc[15]);
    }

    // combine the 4 slots (lanes differing in bits 3,4)
#pragma unroll
    for (int o = 8; o < 32; o <<= 1) {
        sw += __shfl_xor_sync(0xffffffffu, sw, o);
#pragma unroll
        for (int q = 0; q < 16; q++)
            acc[q] += __shfl_xor_sync(0xffffffffu, acc[q], o);
    }

    if (lane < 8) {   // slot 0 holds (redundantly, all do) the totals; lanes 0-7 write
        float inv = 1.0f / (sw + 1e-16f);
#pragma unroll
        for (int q = 0; q < 4; q++) {
            int c = fl * 16 + q * 4;
            float4 b4 = *(const float4*)&bias[c];
            float4 o4;
            o4.x = acc[q*4+0] * inv + b4.x;
            o4.y = acc[q*4+1] * inv + b4.y;
            o4.z = acc[q*4+2] * inv + b4.z;
            o4.w = acc[q*4+3] * inv + b4.w;
            if (do_elu) {
                o4.x = o4.x > 0.f ? o4.x : expm1f(o4.x);
                o4.y = o4.y > 0.f ? o4.y : expm1f(o4.y);
                o4.z = o4.z > 0.f ? o4.z : expm1f(o4.z);
                o4.w = o4.w > 0.f ? o4.w : expm1f(o4.w);
            }
            if (do_pool) {
                int g = __ldg(&batch[d]);
                redAddV4(&g_psum[g * F + c], o4.x, o4.y, o4.z, o4.w);
                atomicMaxFloat(&g_pmax[g * F + c + 0], o4.x);
                atomicMaxFloat(&g_pmax[g * F + c + 1], o4.y);
                atomicMaxFloat(&g_pmax[g * F + c + 2], o4.z);
                atomicMaxFloat(&g_pmax[g * F + c + 3], o4.w);
            } else {
                *(float4*)&O[d * F + c] = o4;
            }
        }
        if (do_pool && lane == 0) atomicAdd(&g_cnt[__ldg(&batch[d])], 1.0f);
    }
}

// ---------------- pooling init + final ----------------
__global__ void pool_init_k() {
    int i = blockIdx.x * blockDim.x + threadIdx.x;
    if (i < GMAX * F) { g_psum[i] = 0.f; g_pmax[i] = -INFINITY; }
    if (i < GMAX) g_cnt[i] = 0.f;
}

__global__ void final_k(const float* __restrict__ lw, const float* __restrict__ lb,
                        float* __restrict__ out) {
    int g    = (blockIdx.x * blockDim.x + threadIdx.x) >> 5;
    int lane = threadIdx.x & 31;
    if (g >= GMAX) return;
    float cnt = fmaxf(g_cnt[g], 1.0f);
    float acc = 0.f;
#pragma unroll
    for (int j = 0; j < 4; j++) {
        int c = lane * 4 + j;
        float mean = g_psum[g * F + c] / cnt;
        float mx = g_pmax[g * F + c];
        if (isinf(mx)) mx = 0.f;
        acc += (mean + mx) * lw[c];
    }
#pragma unroll
    for (int o = 16; o; o >>= 1) acc += __shfl_down_sync(0xffffffffu, acc, o);
    if (lane == 0) out[g] = acc + lb[0];
}

// ---------------- launcher ----------------
extern "C" void kernel_launch(void* const* d_in, const int* in_sizes, int n_in,
                              void* d_out, int out_size) {
    const float* x     = (const float*)d_in[0];
    const int*   ei    = (const int*)d_in[1];
    const int*   batch = (const int*)d_in[2];
    const float* W1    = (const float*)d_in[3];
    const float* as1   = (const float*)d_in[4];
    const float* ad1   = (const float*)d_in[5];
    const float* b1    = (const float*)d_in[6];
    const float* W2    = (const float*)d_in[7];
    const float* as2   = (const float*)d_in[8];
    const float* ad2   = (const float*)d_in[9];
    const float* b2    = (const float*)d_in[10];
    const float* lw    = (const float*)d_in[11];
    const float* lb    = (const float*)d_in[12];

    int N  = in_sizes[0] / F;
    int E  = in_sizes[1] / 2;
    int Et = E + N;

    float *hptr, *bptr;
    cudaGetSymbolAddress((void**)&hptr, g_h);
    cudaGetSymbolAddress((void**)&bptr, g_buf);

    size_t smem = (size_t)(F * XPAD) * sizeof(float);
    cudaFuncSetAttribute(gemm_k, cudaFuncAttributeMaxDynamicSharedMemorySize, (int)smem);

    int gemm_blocks      = (N + 63) / 64;
    int node_warp_blocks = (N * 32 + 255) / 256;
    int edge_blocks      = (Et + 255) / 256;

    // ---- layer 1 (gemm fused with edge count) + CSR build ----
    gemm_k<<<gemm_blocks, 256, smem>>>(x, W1, hptr, as1, ad1, N, ei, E, 1);
    scan_k<<<1, 1024>>>(N);
    scatter_k<<<edge_blocks, 256>>>(ei, E, N);
    aggr_k<<<node_warp_blocks, 256>>>(hptr, bptr, b1, batch, N, 1, 0);   // 4th -> ncu

    // ---- layer 2 ----
    gemm_k<<<gemm_blocks, 256, smem>>>(bptr, W2, hptr, as2, ad2, N, ei, E, 0);
    pool_init_k<<<(GMAX * F + 255) / 256, 256>>>();
    aggr_k<<<node_warp_blocks, 256>>>(hptr, bptr, b2, batch, N, 0, 1);

    // ---- final linear ----
    final_k<<<(GMAX * 32 + 255) / 256, 256>>>(lw, lb, (float*)d_out);
}

// round 9
// speedup vs baseline: 1.5875x; 1.5875x over previous
#include <cuda_runtime.h>
#include <math.h>

#define F      128
#define HEADS  4
#define NMAX   50000
#define GMAX   64
#define EMAX   860000
#define XPAD   68

// ---------------- device scratch ----------------
__device__ __align__(16) float g_h   [NMAX * F];
__device__ __align__(16) float g_buf [NMAX * F];
__device__ __align__(16) float g_as  [NMAX * HEADS];
__device__ __align__(16) float g_ad  [NMAX * HEADS];
__device__ __align__(16) float g_psum[GMAX * F];
__device__ __align__(16) float g_pmax[GMAX * F];
__device__             float g_cnt [GMAX];
__device__ __align__(16) int  g_deg [NMAX];          // zero-init; scan_k restores zeros
__device__             int   g_rowptr[NMAX + 1];
__device__             int   g_wpos[NMAX];
__device__             int   g_csrc[EMAX];

// ---------------- helpers ----------------
__device__ __forceinline__ void atomicMaxFloat(float* addr, float value) {
    if (value >= 0.f) atomicMax((int*)addr, __float_as_int(value));
    else              atomicMin((unsigned int*)addr, __float_as_uint(value));
}

__device__ __forceinline__ void redAddV4(float* p, float a, float b, float c, float d) {
    asm volatile("red.global.add.v4.f32 [%0], {%1,%2,%3,%4};"
                 :: "l"(p), "f"(a), "f"(b), "f"(c), "f"(d) : "memory");
}

// ---------------- GEMM + fused alpha (+ optional edge count) ----------------
__global__ void gemm_k(const float* __restrict__ X, const float* __restrict__ W,
                       float* __restrict__ O,
                       const float* __restrict__ asr, const float* __restrict__ adt,
                       int N, const int* __restrict__ ei, int E, int do_count) {
    extern __shared__ float sm[];
    float* xs = sm;            // [128][XPAD]

    const int tid  = threadIdx.x;
    const int row0 = blockIdx.x * 64;

    if (do_count) {
        int stride = gridDim.x * blockDim.x;
        int Et = E + N;
        for (int i = blockIdx.x * blockDim.x + tid; i < Et; i += stride) {
            int dst = (i < E) ? __ldg(&ei[E + i]) : (i - E);
            atomicAdd(&g_deg[dst], 1);
        }
    }

    const float4* X4 = (const float4*)X;
#pragma unroll
    for (int i = 0; i < 8; i++) {
        int idx = tid + i * 256;
        int r = idx >> 5, kq = idx & 31;
        float4 v = make_float4(0.f, 0.f, 0.f, 0.f);
        int gr = row0 + r;
        if (gr < N) v = X4[gr * 32 + kq];
        xs[(4 * kq + 0) * XPAD + r] = v.x;
        xs[(4 * kq + 1) * XPAD + r] = v.y;
        xs[(4 * kq + 2) * XPAD + r] = v.z;
        xs[(4 * kq + 3) * XPAD + r] = v.w;
    }
    __syncthreads();

    const int ty = tid >> 4, tx = tid & 15;
    float acc[4][8];
#pragma unroll
    for (int i = 0; i < 4; i++)
#pragma unroll
        for (int j = 0; j < 8; j++) acc[i][j] = 0.f;

#pragma unroll 4
    for (int k = 0; k < F; k++) {
        float4 x4 = *(const float4*)&xs[k * XPAD + ty * 4];
        float xr[4] = {x4.x, x4.y, x4.z, x4.w};
        float4 w0 = __ldg((const float4*)&W[k * F + tx * 8]);
        float4 w1 = __ldg((const float4*)&W[k * F + tx * 8 + 4]);
        float wr[8] = {w0.x, w0.y, w0.z, w0.w, w1.x, w1.y, w1.z, w1.w};
#pragma unroll
        for (int i = 0; i < 4; i++)
#pragma unroll
            for (int j = 0; j < 8; j++) acc[i][j] = fmaf(xr[i], wr[j], acc[i][j]);
    }

    float4 a0 = *(const float4*)&asr[tx * 8];
    float4 a1 = *(const float4*)&asr[tx * 8 + 4];
    float4 d0 = *(const float4*)&adt[tx * 8];
    float4 d1 = *(const float4*)&adt[tx * 8 + 4];
    float av[8] = {a0.x, a0.y, a0.z, a0.w, a1.x, a1.y, a1.z, a1.w};
    float dv[8] = {d0.x, d0.y, d0.z, d0.w, d1.x, d1.y, d1.z, d1.w};

    const int lane = tid & 31;
    const int head = (lane >> 2) & 3;

#pragma unroll
    for (int i = 0; i < 4; i++) {
        int gr = row0 + ty * 4 + i;
        float ps = 0.f, pd = 0.f;
#pragma unroll
        for (int j = 0; j < 8; j++) {
            ps = fmaf(acc[i][j], av[j], ps);
            pd = fmaf(acc[i][j], dv[j], pd);
        }
        ps += __shfl_down_sync(0xffffffffu, ps, 1, 4);
        ps += __shfl_down_sync(0xffffffffu, ps, 2, 4);
        pd += __shfl_down_sync(0xffffffffu, pd, 1, 4);
        pd += __shfl_down_sync(0xffffffffu, pd, 2, 4);
        if (gr < N) {
            if ((lane & 3) == 0) {
                g_as[gr * 4 + head] = ps;
                g_ad[gr * 4 + head] = pd;
            }
            *(float4*)&O[gr * F + tx * 8]     = make_float4(acc[i][0], acc[i][1], acc[i][2], acc[i][3]);
            *(float4*)&O[gr * F + tx * 8 + 4] = make_float4(acc[i][4], acc[i][5], acc[i][6], acc[i][7]);
        }
    }
}

// ---------------- single-block scan, 4 items/thread; zeros g_deg ----------------
__global__ void scan_k(int N) {
    __shared__ int warpsum[32];
    __shared__ int carry_s;
    int tid = threadIdx.x, lane = tid & 31, wid = tid >> 5;
    if (tid == 0) carry_s = 0;
    __syncthreads();
    for (int base = 0; base < N; base += 4096) {
        int i = base + tid * 4;
        int4 v = make_int4(0, 0, 0, 0);
        bool full = (i + 3 < N);
        if (full) v = *(const int4*)&g_deg[i];
        else if (i < N) {
            v.x = g_deg[i];
            if (i + 1 < N) v.y = g_deg[i + 1];
            if (i + 2 < N) v.z = g_deg[i + 2];
        }
        int t1 = v.x + v.y, t2 = t1 + v.z, t3 = t2 + v.w;
        int x = t3;
#pragma unroll
        for (int o = 1; o < 32; o <<= 1) {
            int t = __shfl_up_sync(0xffffffffu, x, o);
            if (lane >= o) x += t;
        }
        if (lane == 31) warpsum[wid] = x;
        __syncthreads();
        if (wid == 0) {
            int s = warpsum[lane];
#pragma unroll
            for (int o = 1; o < 32; o <<= 1) {
                int t = __shfl_up_sync(0xffffffffu, s, o);
                if (lane >= o) s += t;
            }
            warpsum[lane] = s;
        }
        __syncthreads();
        int c    = carry_s;
        int pref = (wid > 0) ? warpsum[wid - 1] : 0;
        int e0 = c + pref + (x - t3);
        if (full) {
            g_rowptr[i] = e0;       g_wpos[i]     = e0;
            g_rowptr[i+1] = e0+v.x; g_wpos[i+1]   = e0+v.x;
            g_rowptr[i+2] = e0+t1;  g_wpos[i+2]   = e0+t1;
            g_rowptr[i+3] = e0+t2;  g_wpos[i+3]   = e0+t2;
            *(int4*)&g_deg[i] = make_int4(0, 0, 0, 0);
        } else if (i < N) {
            g_rowptr[i] = e0; g_wpos[i] = e0; g_deg[i] = 0;
            if (i+1 < N) { g_rowptr[i+1] = e0+v.x; g_wpos[i+1] = e0+v.x; g_deg[i+1] = 0; }
            if (i+2 < N) { g_rowptr[i+2] = e0+t1;  g_wpos[i+2] = e0+t1;  g_deg[i+2] = 0; }
        }
        __syncthreads();
        if (tid == 1023) carry_s = c + pref + x;
        __syncthreads();
    }
    if (threadIdx.x == 0) g_rowptr[N] = carry_s;
}

__global__ void scatter_k(const int* __restrict__ ei, int E, int N) {
    int i = blockIdx.x * blockDim.x + threadIdx.x;
    int Et = E + N;
    if (i >= Et) return;
    int src, dst;
    if (i < E) { src = ei[i]; dst = ei[E + i]; }
    else       { src = dst = i - E; }
    int pos = atomicAdd(&g_wpos[dst], 1);
    g_csrc[pos] = src;
}

// ---------------- fused softmax + aggregation + bias (+ELU / +pool), warp per dst ----------------
// R6 form: contiguous row read per edge, depth-1 value prefetch, single accumulator.
__global__ void __launch_bounds__(256)
aggr_k(const float* __restrict__ Hm,
       float* __restrict__ O,
       const float* __restrict__ bias,
       const int* __restrict__ batch,
       int N, int do_elu, int do_pool) {
    int d    = (blockIdx.x * blockDim.x + threadIdx.x) >> 5;
    int lane = threadIdx.x & 31;
    if (d >= N) return;
    int head = lane >> 3;

    float adh = g_ad[d * 4 + head];
    int i0 = g_rowptr[d];
    int i1 = g_rowptr[d + 1];

    float4 acc = make_float4(0.f, 0.f, 0.f, 0.f);
    float sw = 0.f;

    float  a_next  = 0.f;
    float4 hv_next = make_float4(0.f, 0.f, 0.f, 0.f);
    if (i0 < i1) {
        int sn = __ldg(&g_csrc[i0]);
        a_next  = __ldg(&g_as[sn * 4 + head]);
        hv_next = *(const float4*)&Hm[sn * F + lane * 4];
    }

    for (int i = i0; i < i1; i++) {
        float  a  = a_next;
        float4 hv = hv_next;
        if (i + 1 < i1) {
            int sn = __ldg(&g_csrc[i + 1]);
            a_next  = __ldg(&g_as[sn * 4 + head]);
            hv_next = *(const float4*)&Hm[sn * F + lane * 4];
        }
        float e = a + adh;
        e = e > 0.f ? e : 0.2f * e;
        float w = __expf(e);
        sw += w;
        acc.x = fmaf(w, hv.x, acc.x);
        acc.y = fmaf(w, hv.y, acc.y);
        acc.z = fmaf(w, hv.z, acc.z);
        acc.w = fmaf(w, hv.w, acc.w);
    }

    float inv = 1.0f / (sw + 1e-16f);
    float4 b4 = *(const float4*)&bias[lane * 4];
    float4 o;
    o.x = acc.x * inv + b4.x;
    o.y = acc.y * inv + b4.y;
    o.z = acc.z * inv + b4.z;
    o.w = acc.w * inv + b4.w;
    if (do_elu) {
        o.x = o.x > 0.f ? o.x : expm1f(o.x);
        o.y = o.y > 0.f ? o.y : expm1f(o.y);
        o.z = o.z > 0.f ? o.z : expm1f(o.z);
        o.w = o.w > 0.f ? o.w : expm1f(o.w);
    }

    if (do_pool) {
        int g = __ldg(&batch[d]);
        redAddV4(&g_psum[g * F + lane * 4], o.x, o.y, o.z, o.w);
        atomicMaxFloat(&g_pmax[g * F + lane * 4 + 0], o.x);
        atomicMaxFloat(&g_pmax[g * F + lane * 4 + 1], o.y);
        atomicMaxFloat(&g_pmax[g * F + lane * 4 + 2], o.z);
        atomicMaxFloat(&g_pmax[g * F + lane * 4 + 3], o.w);
        if (lane == 0) atomicAdd(&g_cnt[g], 1.0f);
    } else {
        *(float4*)&O[d * F + lane * 4] = o;
    }
}

// ---------------- pooling init + final ----------------
__global__ void pool_init_k() {
    int i = blockIdx.x * blockDim.x + threadIdx.x;
    if (i < GMAX * F) { g_psum[i] = 0.f; g_pmax[i] = -INFINITY; }
    if (i < GMAX) g_cnt[i] = 0.f;
}

__global__ void final_k(const float* __restrict__ lw, const float* __restrict__ lb,
                        float* __restrict__ out) {
    int g    = (blockIdx.x * blockDim.x + threadIdx.x) >> 5;
    int lane = threadIdx.x & 31;
    if (g >= GMAX) return;
    float cnt = fmaxf(g_cnt[g], 1.0f);
    float acc = 0.f;
#pragma unroll
    for (int j = 0; j < 4; j++) {
        int c = lane * 4 + j;
        float mean = g_psum[g * F + c] / cnt;
        float mx = g_pmax[g * F + c];
        if (isinf(mx)) mx = 0.f;
        acc += (mean + mx) * lw[c];
    }
#pragma unroll
    for (int o = 16; o; o >>= 1) acc += __shfl_down_sync(0xffffffffu, acc, o);
    if (lane == 0) out[g] = acc + lb[0];
}

// ---------------- launcher ----------------
extern "C" void kernel_launch(void* const* d_in, const int* in_sizes, int n_in,
                              void* d_out, int out_size) {
    const float* x     = (const float*)d_in[0];
    const int*   ei    = (const int*)d_in[1];
    const int*   batch = (const int*)d_in[2];
    const float* W1    = (const float*)d_in[3];
    const float* as1   = (const float*)d_in[4];
    const float* ad1   = (const float*)d_in[5];
    const float* b1    = (const float*)d_in[6];
    const float* W2    = (const float*)d_in[7];
    const float* as2   = (const float*)d_in[8];
    const float* ad2   = (const float*)d_in[9];
    const float* b2    = (const float*)d_in[10];
    const float* lw    = (const float*)d_in[11];
    const float* lb    = (const float*)d_in[12];

    int N  = in_sizes[0] / F;
    int E  = in_sizes[1] / 2;
    int Et = E + N;

    float *hptr, *bptr;
    cudaGetSymbolAddress((void**)&hptr, g_h);
    cudaGetSymbolAddress((void**)&bptr, g_buf);

    size_t smem = (size_t)(F * XPAD) * sizeof(float);
    cudaFuncSetAttribute(gemm_k, cudaFuncAttributeMaxDynamicSharedMemorySize, (int)smem);

    int gemm_blocks      = (N + 63) / 64;
    int node_warp_blocks = (N * 32 + 255) / 256;
    int edge_blocks      = (Et + 255) / 256;

    // ---- layer 1 (gemm fused with edge count) + CSR build ----
    gemm_k<<<gemm_blocks, 256, smem>>>(x, W1, hptr, as1, ad1, N, ei, E, 1);
    scan_k<<<1, 1024>>>(N);
    scatter_k<<<edge_blocks, 256>>>(ei, E, N);
    aggr_k<<<node_warp_blocks, 256>>>(hptr, bptr, b1, batch, N, 1, 0);   // 4th -> ncu

    // ---- layer 2 ----
    gemm_k<<<gemm_blocks, 256, smem>>>(bptr, W2, hptr, as2, ad2, N, ei, E, 0);
    pool_init_k<<<(GMAX * F + 255) / 256, 256>>>();
    aggr_k<<<node_warp_blocks, 256>>>(hptr, bptr, b2, batch, N, 0, 1);

    // ---- final linear ----
    final_k<<<(GMAX * 32 + 255) / 256, 256>>>(lw, lb, (float*)d_out);
}

// round 11
// speedup vs baseline: 2.2383x; 1.4099x over previous
#include <cuda_runtime.h>
#include <math.h>

#define F      128
#define HEADS  4
#define NMAX   50000
#define GMAX   64
#define EMAX   860000
#define XPAD2  132

// ---------------- device scratch ----------------
__device__ __align__(16) float g_h   [NMAX * F];
__device__ __align__(16) float g_buf [NMAX * F];
__device__ __align__(16) float g_as  [NMAX * HEADS];
__device__ __align__(16) float g_ad  [NMAX * HEADS];
__device__ __align__(16) int  g_deg [NMAX];          // zero-init; scan_k restores zeros
__device__             int   g_rowptr[NMAX + 1];
__device__             int   g_wpos[NMAX];
__device__             int   g_csrc[EMAX];

// ---------------- GEMM 128x128 tile + fused alpha (+ optional edge count) ----------------
__global__ void __launch_bounds__(256, 2)
gemm_k(const float* __restrict__ X, const float* __restrict__ W,
       float* __restrict__ O,
       const float* __restrict__ asr, const float* __restrict__ adt,
       int N, const int* __restrict__ ei, int E, int do_count) {
    extern __shared__ float xs[];          // [128][XPAD2] transposed: xs[k][row]

    const int tid  = threadIdx.x;
    const int row0 = blockIdx.x * 128;

    if (do_count) {
        int stride = gridDim.x * blockDim.x;
        int Et = E + N;
        for (int i = blockIdx.x * blockDim.x + tid; i < Et; i += stride) {
            int dst = (i < E) ? __ldg(&ei[E + i]) : (i - E);
            atomicAdd(&g_deg[dst], 1);
        }
    }

    const float4* X4 = (const float4*)X;
#pragma unroll
    for (int i = 0; i < 16; i++) {
        int idx = tid + i * 256;           // 0..4095
        int r = idx >> 5, kq = idx & 31;
        float4 v = make_float4(0.f, 0.f, 0.f, 0.f);
        int gr = row0 + r;
        if (gr < N) v = X4[gr * 32 + kq];
        xs[(4 * kq + 0) * XPAD2 + r] = v.x;
        xs[(4 * kq + 1) * XPAD2 + r] = v.y;
        xs[(4 * kq + 2) * XPAD2 + r] = v.z;
        xs[(4 * kq + 3) * XPAD2 + r] = v.w;
    }
    __syncthreads();

    const int ty = tid >> 4, tx = tid & 15;   // 8 rows, 8 cols per thread
    float acc[8][8];
#pragma unroll
    for (int i = 0; i < 8; i++)
#pragma unroll
        for (int j = 0; j < 8; j++) acc[i][j] = 0.f;

#pragma unroll 2
    for (int k = 0; k < F; k++) {
        float4 xa = *(const float4*)&xs[k * XPAD2 + ty * 8];
        float4 xb = *(const float4*)&xs[k * XPAD2 + ty * 8 + 4];
        float xr[8] = {xa.x, xa.y, xa.z, xa.w, xb.x, xb.y, xb.z, xb.w};
        float4 w0 = __ldg((const float4*)&W[k * F + tx * 8]);
        float4 w1 = __ldg((const float4*)&W[k * F + tx * 8 + 4]);
        float wr[8] = {w0.x, w0.y, w0.z, w0.w, w1.x, w1.y, w1.z, w1.w};
#pragma unroll
        for (int i = 0; i < 8; i++)
#pragma unroll
            for (int j = 0; j < 8; j++) acc[i][j] = fmaf(xr[i], wr[j], acc[i][j]);
    }

    float4 a0 = *(const float4*)&asr[tx * 8];
    float4 a1 = *(const float4*)&asr[tx * 8 + 4];
    float4 d0 = *(const float4*)&adt[tx * 8];
    float4 d1 = *(const float4*)&adt[tx * 8 + 4];
    float av[8] = {a0.x, a0.y, a0.z, a0.w, a1.x, a1.y, a1.z, a1.w};
    float dv[8] = {d0.x, d0.y, d0.z, d0.w, d1.x, d1.y, d1.z, d1.w};

    const int lane = tid & 31;
    const int head = (lane >> 2) & 3;

#pragma unroll
    for (int i = 0; i < 8; i++) {
        int gr = row0 + ty * 8 + i;
        float ps = 0.f, pd = 0.f;
#pragma unroll
        for (int j = 0; j < 8; j++) {
            ps = fmaf(acc[i][j], av[j], ps);
            pd = fmaf(acc[i][j], dv[j], pd);
        }
        ps += __shfl_down_sync(0xffffffffu, ps, 1, 4);
        ps += __shfl_down_sync(0xffffffffu, ps, 2, 4);
        pd += __shfl_down_sync(0xffffffffu, pd, 1, 4);
        pd += __shfl_down_sync(0xffffffffu, pd, 2, 4);
        if (gr < N) {
            if ((lane & 3) == 0) {
                g_as[gr * 4 + head] = ps;
                g_ad[gr * 4 + head] = pd;
            }
            *(float4*)&O[gr * F + tx * 8]     = make_float4(acc[i][0], acc[i][1], acc[i][2], acc[i][3]);
            *(float4*)&O[gr * F + tx * 8 + 4] = make_float4(acc[i][4], acc[i][5], acc[i][6], acc[i][7]);
        }
    }
}

// ---------------- single-block scan, 4 items/thread; zeros g_deg ----------------
__global__ void scan_k(int N) {
    __shared__ int warpsum[32];
    __shared__ int carry_s;
    int tid = threadIdx.x, lane = tid & 31, wid = tid >> 5;
    if (tid == 0) carry_s = 0;
    __syncthreads();
    for (int base = 0; base < N; base += 4096) {
        int i = base + tid * 4;
        int4 v = make_int4(0, 0, 0, 0);
        bool full = (i + 3 < N);
        if (full) v = *(const int4*)&g_deg[i];
        else if (i < N) {
            v.x = g_deg[i];
            if (i + 1 < N) v.y = g_deg[i + 1];
            if (i + 2 < N) v.z = g_deg[i + 2];
        }
        int t1 = v.x + v.y, t2 = t1 + v.z, t3 = t2 + v.w;
        int x = t3;
#pragma unroll
        for (int o = 1; o < 32; o <<= 1) {
            int t = __shfl_up_sync(0xffffffffu, x, o);
            if (lane >= o) x += t;
        }
        if (lane == 31) warpsum[wid] = x;
        __syncthreads();
        if (wid == 0) {
            int s = warpsum[lane];
#pragma unroll
            for (int o = 1; o < 32; o <<= 1) {
                int t = __shfl_up_sync(0xffffffffu, s, o);
                if (lane >= o) s += t;
            }
            warpsum[lane] = s;
        }
        __syncthreads();
        int c    = carry_s;
        int pref = (wid > 0) ? warpsum[wid - 1] : 0;
        int e0 = c + pref + (x - t3);
        if (full) {
            g_rowptr[i] = e0;       g_wpos[i]     = e0;
            g_rowptr[i+1] = e0+v.x; g_wpos[i+1]   = e0+v.x;
            g_rowptr[i+2] = e0+t1;  g_wpos[i+2]   = e0+t1;
            g_rowptr[i+3] = e0+t2;  g_wpos[i+3]   = e0+t2;
            *(int4*)&g_deg[i] = make_int4(0, 0, 0, 0);
        } else if (i < N) {
            g_rowptr[i] = e0; g_wpos[i] = e0; g_deg[i] = 0;
            if (i+1 < N) { g_rowptr[i+1] = e0+v.x; g_wpos[i+1] = e0+v.x; g_deg[i+1] = 0; }
            if (i+2 < N) { g_rowptr[i+2] = e0+t1;  g_wpos[i+2] = e0+t1;  g_deg[i+2] = 0; }
        }
        __syncthreads();
        if (tid == 1023) carry_s = c + pref + x;
        __syncthreads();
    }
    if (threadIdx.x == 0) g_rowptr[N] = carry_s;
}

__global__ void scatter_k(const int* __restrict__ ei, int E, int N) {
    int i = blockIdx.x * blockDim.x + threadIdx.x;
    int Et = E + N;
    if (i >= Et) return;
    int src, dst;
    if (i < E) { src = ei[i]; dst = ei[E + i]; }
    else       { src = dst = i - E; }
    int pos = atomicAdd(&g_wpos[dst], 1);
    g_csrc[pos] = src;
}

// ---------------- fused softmax + aggregation + bias (+ELU), warp per dst ----------------
__global__ void __launch_bounds__(256)
aggr_k(const float* __restrict__ Hm,
       float* __restrict__ O,
       const float* __restrict__ bias,
       int N, int do_elu) {
    int d    = (blockIdx.x * blockDim.x + threadIdx.x) >> 5;
    int lane = threadIdx.x & 31;
    if (d >= N) return;
    int head = lane >> 3;

    float adh = g_ad[d * 4 + head];
    int i0 = g_rowptr[d];
    int i1 = g_rowptr[d + 1];

    float4 acc = make_float4(0.f, 0.f, 0.f, 0.f);
    float sw = 0.f;

    float  a_next  = 0.f;
    float4 hv_next = make_float4(0.f, 0.f, 0.f, 0.f);
    if (i0 < i1) {
        int sn = __ldg(&g_csrc[i0]);
        a_next  = __ldg(&g_as[sn * 4 + head]);
        hv_next = *(const float4*)&Hm[sn * F + lane * 4];
    }

    for (int i = i0; i < i1; i++) {
        float  a  = a_next;
        float4 hv = hv_next;
        if (i + 1 < i1) {
            int sn = __ldg(&g_csrc[i + 1]);
            a_next  = __ldg(&g_as[sn * 4 + head]);
            hv_next = *(const float4*)&Hm[sn * F + lane * 4];
        }
        float e = a + adh;
        e = e > 0.f ? e : 0.2f * e;
        float w = __expf(e);
        sw += w;
        acc.x = fmaf(w, hv.x, acc.x);
        acc.y = fmaf(w, hv.y, acc.y);
        acc.z = fmaf(w, hv.z, acc.z);
        acc.w = fmaf(w, hv.w, acc.w);
    }

    float inv = 1.0f / (sw + 1e-16f);
    float4 b4 = *(const float4*)&bias[lane * 4];
    float4 o;
    o.x = acc.x * inv + b4.x;
    o.y = acc.y * inv + b4.y;
    o.z = acc.z * inv + b4.z;
    o.w = acc.w * inv + b4.w;
    if (do_elu) {
        o.x = o.x > 0.f ? o.x : expm1f(o.x);
        o.y = o.y > 0.f ? o.y : expm1f(o.y);
        o.z = o.z > 0.f ? o.z : expm1f(o.z);
        o.w = o.w > 0.f ? o.w : expm1f(o.w);
    }
    *(float4*)&O[d * F + lane * 4] = o;
}

// ---------------- pooling + final linear (one block per graph, no atomics) ----------------
__global__ void pool_final_k(const float* __restrict__ B,
                             const int* __restrict__ batch,
                             const float* __restrict__ lw,
                             const float* __restrict__ lb,
                             float* __restrict__ out, int N) {
    int g = blockIdx.x;
    int c = threadIdx.x;     // feature 0..127

    // batch is sorted: binary search for [start, end) of graph g
    int lo = 0, hi = N;
    while (lo < hi) { int mid = (lo + hi) >> 1; if (__ldg(&batch[mid]) < g) lo = mid + 1; else hi = mid; }
    int start = lo;
    hi = N;
    while (lo < hi) { int mid = (lo + hi) >> 1; if (__ldg(&batch[mid]) < g + 1) lo = mid + 1; else hi = mid; }
    int end = lo;

    float sum = 0.f, mx = -INFINITY;
    int n = start;
    for (; n + 3 < end; n += 4) {
        float v0 = __ldg(&B[(n + 0) * F + c]);
        float v1 = __ldg(&B[(n + 1) * F + c]);
        float v2 = __ldg(&B[(n + 2) * F + c]);
        float v3 = __ldg(&B[(n + 3) * F + c]);
        sum += (v0 + v1) + (v2 + v3);
        mx = fmaxf(mx, fmaxf(fmaxf(v0, v1), fmaxf(v2, v3)));
    }
    for (; n < end; n++) {
        float v = __ldg(&B[n * F + c]);
        sum += v; mx = fmaxf(mx, v);
    }
    float cnt = fmaxf((float)(end - start), 1.0f);
    if (isinf(mx)) mx = 0.f;
    float val = (sum / cnt + mx) * __ldg(&lw[c]);

    __shared__ float red[128];
    red[c] = val;
    __syncthreads();
#pragma unroll
    for (int o = 64; o; o >>= 1) {
        if (c < o) red[c] += red[c + o];
        __syncthreads();
    }
    if (c == 0) out[g] = red[0] + __ldg(&lb[0]);
}

// ---------------- launcher ----------------
extern "C" void kernel_launch(void* const* d_in, const int* in_sizes, int n_in,
                              void* d_out, int out_size) {
    const float* x     = (const float*)d_in[0];
    const int*   ei    = (const int*)d_in[1];
    const int*   batch = (const int*)d_in[2];
    const float* W1    = (const float*)d_in[3];
    const float* as1   = (const float*)d_in[4];
    const float* ad1   = (const float*)d_in[5];
    const float* b1    = (const float*)d_in[6];
    const float* W2    = (const float*)d_in[7];
    const float* as2   = (const float*)d_in[8];
    const float* ad2   = (const float*)d_in[9];
    const float* b2    = (const float*)d_in[10];
    const float* lw    = (const float*)d_in[11];
    const float* lb    = (const float*)d_in[12];

    int N  = in_sizes[0] / F;
    int E  = in_sizes[1] / 2;
    int Et = E + N;

    float *hptr, *bptr;
    cudaGetSymbolAddress((void**)&hptr, g_h);
    cudaGetSymbolAddress((void**)&bptr, g_buf);

    size_t smem = (size_t)(F * XPAD2) * sizeof(float);
    cudaFuncSetAttribute(gemm_k, cudaFuncAttributeMaxDynamicSharedMemorySize, (int)smem);

    int gemm_blocks      = (N + 127) / 128;
    int node_warp_blocks = (N * 32 + 255) / 256;
    int edge_blocks      = (Et + 255) / 256;

    // ---- layer 1 (gemm fused with edge count) + CSR build ----
    gemm_k<<<gemm_blocks, 256, smem>>>(x, W1, hptr, as1, ad1, N, ei, E, 1);
    scan_k<<<1, 1024>>>(N);
    scatter_k<<<edge_blocks, 256>>>(ei, E, N);
    aggr_k<<<node_warp_blocks, 256>>>(hptr, bptr, b1, N, 1);   // 4th -> ncu

    // ---- layer 2 ----
    gemm_k<<<gemm_blocks, 256, smem>>>(bptr, W2, hptr, as2, ad2, N, ei, E, 0);
    aggr_k<<<node_warp_blocks, 256>>>(hptr, bptr, b2, N, 0);

    // ---- pooling + final linear (no atomics) ----
    pool_final_k<<<GMAX, 128>>>(bptr, batch, lw, lb, (float*)d_out, N);
}

// round 12
// speedup vs baseline: 2.2533x; 1.0067x over previous
#include <cuda_runtime.h>
#include <math.h>

#define F      128
#define HEADS  4
#define NMAX   50000
#define GMAX   64
#define EMAX   860000
#define XPAD2  132

// ---------------- device scratch ----------------
__device__ __align__(16) float g_h   [NMAX * F];
__device__ __align__(16) float g_buf [NMAX * F];
__device__ __align__(16) float g_as  [NMAX * HEADS];
__device__ __align__(16) float g_ad  [NMAX * HEADS];
__device__ __align__(16) float g_w   [EMAX * HEADS];   // per-(CSR slot, head) softmax weight
__device__ __align__(16) int  g_deg [NMAX];            // zero-init; scan_k restores zeros
__device__             int   g_rowptr[NMAX + 1];
__device__             int   g_wpos[NMAX];
__device__             int   g_csrc[EMAX];
__device__             int   g_cdst[EMAX];

// ---------------- GEMM 128x128 tile + fused alpha ----------------
__global__ void __launch_bounds__(256, 2)
gemm_k(const float* __restrict__ X, const float* __restrict__ W,
       float* __restrict__ O,
       const float* __restrict__ asr, const float* __restrict__ adt,
       int N) {
    extern __shared__ float xs[];          // [128][XPAD2] transposed: xs[k][row]

    const int tid  = threadIdx.x;
    const int row0 = blockIdx.x * 128;

    const float4* X4 = (const float4*)X;
#pragma unroll
    for (int i = 0; i < 16; i++) {
        int idx = tid + i * 256;           // 0..4095
        int r = idx >> 5, kq = idx & 31;
        float4 v = make_float4(0.f, 0.f, 0.f, 0.f);
        int gr = row0 + r;
        if (gr < N) v = X4[gr * 32 + kq];
        xs[(4 * kq + 0) * XPAD2 + r] = v.x;
        xs[(4 * kq + 1) * XPAD2 + r] = v.y;
        xs[(4 * kq + 2) * XPAD2 + r] = v.z;
        xs[(4 * kq + 3) * XPAD2 + r] = v.w;
    }
    __syncthreads();

    const int ty = tid >> 4, tx = tid & 15;   // 8 rows, 8 cols per thread
    float acc[8][8];
#pragma unroll
    for (int i = 0; i < 8; i++)
#pragma unroll
        for (int j = 0; j < 8; j++) acc[i][j] = 0.f;

#pragma unroll 2
    for (int k = 0; k < F; k++) {
        float4 xa = *(const float4*)&xs[k * XPAD2 + ty * 8];
        float4 xb = *(const float4*)&xs[k * XPAD2 + ty * 8 + 4];
        float xr[8] = {xa.x, xa.y, xa.z, xa.w, xb.x, xb.y, xb.z, xb.w};
        float4 w0 = __ldg((const float4*)&W[k * F + tx * 8]);
        float4 w1 = __ldg((const float4*)&W[k * F + tx * 8 + 4]);
        float wr[8] = {w0.x, w0.y, w0.z, w0.w, w1.x, w1.y, w1.z, w1.w};
#pragma unroll
        for (int i = 0; i < 8; i++)
#pragma unroll
            for (int j = 0; j < 8; j++) acc[i][j] = fmaf(xr[i], wr[j], acc[i][j]);
    }

    float4 a0 = *(const float4*)&asr[tx * 8];
    float4 a1 = *(const float4*)&asr[tx * 8 + 4];
    float4 d0 = *(const float4*)&adt[tx * 8];
    float4 d1 = *(const float4*)&adt[tx * 8 + 4];
    float av[8] = {a0.x, a0.y, a0.z, a0.w, a1.x, a1.y, a1.z, a1.w};
    float dv[8] = {d0.x, d0.y, d0.z, d0.w, d1.x, d1.y, d1.z, d1.w};

    const int lane = tid & 31;
    const int head = (lane >> 2) & 3;

#pragma unroll
    for (int i = 0; i < 8; i++) {
        int gr = row0 + ty * 8 + i;
        float ps = 0.f, pd = 0.f;
#pragma unroll
        for (int j = 0; j < 8; j++) {
            ps = fmaf(acc[i][j], av[j], ps);
            pd = fmaf(acc[i][j], dv[j], pd);
        }
        ps += __shfl_down_sync(0xffffffffu, ps, 1, 4);
        ps += __shfl_down_sync(0xffffffffu, ps, 2, 4);
        pd += __shfl_down_sync(0xffffffffu, pd, 1, 4);
        pd += __shfl_down_sync(0xffffffffu, pd, 2, 4);
        if (gr < N) {
            if ((lane & 3) == 0) {
                g_as[gr * 4 + head] = ps;
                g_ad[gr * 4 + head] = pd;
            }
            *(float4*)&O[gr * F + tx * 8]     = make_float4(acc[i][0], acc[i][1], acc[i][2], acc[i][3]);
            *(float4*)&O[gr * F + tx * 8 + 4] = make_float4(acc[i][4], acc[i][5], acc[i][6], acc[i][7]);
        }
    }
}

// ---------------- CSR build ----------------
__global__ void count_k(const int* __restrict__ ei, int E, int N) {
    int i = blockIdx.x * blockDim.x + threadIdx.x;
    int Et = E + N;
    if (i >= Et) return;
    int dst = (i < E) ? __ldg(&ei[E + i]) : (i - E);
    atomicAdd(&g_deg[dst], 1);
}

// single-block scan, 4 items/thread; zeros g_deg
__global__ void scan_k(int N) {
    __shared__ int warpsum[32];
    __shared__ int carry_s;
    int tid = threadIdx.x, lane = tid & 31, wid = tid >> 5;
    if (tid == 0) carry_s = 0;
    __syncthreads();
    for (int base = 0; base < N; base += 4096) {
        int i = base + tid * 4;
        int4 v = make_int4(0, 0, 0, 0);
        bool full = (i + 3 < N);
        if (full) v = *(const int4*)&g_deg[i];
        else if (i < N) {
            v.x = g_deg[i];
            if (i + 1 < N) v.y = g_deg[i + 1];
            if (i + 2 < N) v.z = g_deg[i + 2];
        }
        int t1 = v.x + v.y, t2 = t1 + v.z, t3 = t2 + v.w;
        int x = t3;
#pragma unroll
        for (int o = 1; o < 32; o <<= 1) {
            int t = __shfl_up_sync(0xffffffffu, x, o);
            if (lane >= o) x += t;
        }
        if (lane == 31) warpsum[wid] = x;
        __syncthreads();
        if (wid == 0) {
            int s = warpsum[lane];
#pragma unroll
            for (int o = 1; o < 32; o <<= 1) {
                int t = __shfl_up_sync(0xffffffffu, s, o);
                if (lane >= o) s += t;
            }
            warpsum[lane] = s;
        }
        __syncthreads();
        int c    = carry_s;
        int pref = (wid > 0) ? warpsum[wid - 1] : 0;
        int e0 = c + pref + (x - t3);
        if (full) {
            g_rowptr[i] = e0;       g_wpos[i]     = e0;
            g_rowptr[i+1] = e0+v.x; g_wpos[i+1]   = e0+v.x;
            g_rowptr[i+2] = e0+t1;  g_wpos[i+2]   = e0+t1;
            g_rowptr[i+3] = e0+t2;  g_wpos[i+3]   = e0+t2;
            *(int4*)&g_deg[i] = make_int4(0, 0, 0, 0);
        } else if (i < N) {
            g_rowptr[i] = e0; g_wpos[i] = e0; g_deg[i] = 0;
            if (i+1 < N) { g_rowptr[i+1] = e0+v.x; g_wpos[i+1] = e0+v.x; g_deg[i+1] = 0; }
            if (i+2 < N) { g_rowptr[i+2] = e0+t1;  g_wpos[i+2] = e0+t1;  g_deg[i+2] = 0; }
        }
        __syncthreads();
        if (tid == 1023) carry_s = c + pref + x;
        __syncthreads();
    }
    if (threadIdx.x == 0) g_rowptr[N] = carry_s;
}

__global__ void scatter_k(const int* __restrict__ ei, int E, int N) {
    int i = blockIdx.x * blockDim.x + threadIdx.x;
    int Et = E + N;
    if (i >= Et) return;
    int src, dst;
    if (i < E) { src = ei[i]; dst = ei[E + i]; }
    else       { src = dst = i - E; }
    int pos = atomicAdd(&g_wpos[dst], 1);
    g_csrc[pos] = src;
    g_cdst[pos] = dst;
}

// ---------------- edge weight precompute: w[i][h] = exp(leaky(as[src][h]+ad[dst][h])) ----------------
__global__ void wk_k(int Et) {
    int i = blockIdx.x * blockDim.x + threadIdx.x;
    if (i >= Et) return;
    int s = g_csrc[i];
    int d = g_cdst[i];
    float4 a = *(const float4*)&g_as[s * 4];
    float4 b = *(const float4*)&g_ad[d * 4];
    float4 w;
    float e;
    e = a.x + b.x; e = e > 0.f ? e : 0.2f * e; w.x = __expf(e);
    e = a.y + b.y; e = e > 0.f ? e : 0.2f * e; w.y = __expf(e);
    e = a.z + b.z; e = e > 0.f ? e : 0.2f * e; w.z = __expf(e);
    e = a.w + b.w; e = e > 0.f ? e : 0.2f * e; w.w = __expf(e);
    *(float4*)&g_w[i * 4] = w;
}

// ---------------- aggregation + bias (+ELU), warp per dst, weights precomputed ----------------
__global__ void __launch_bounds__(256)
aggr_k(const float* __restrict__ Hm,
       float* __restrict__ O,
       const float* __restrict__ bias,
       int N, int do_elu) {
    int d    = (blockIdx.x * blockDim.x + threadIdx.x) >> 5;
    int lane = threadIdx.x & 31;
    if (d >= N) return;
    int head = lane >> 3;

    int i0 = g_rowptr[d];
    int i1 = g_rowptr[d + 1];

    float4 acc = make_float4(0.f, 0.f, 0.f, 0.f);
    float sw = 0.f;

    float  w_next  = 0.f;
    float4 hv_next = make_float4(0.f, 0.f, 0.f, 0.f);
    if (i0 < i1) {
        int sn = __ldg(&g_csrc[i0]);
        w_next  = __ldg(&g_w[i0 * 4 + head]);
        hv_next = *(const float4*)&Hm[sn * F + lane * 4];
    }

    for (int i = i0; i < i1; i++) {
        float  w  = w_next;
        float4 hv = hv_next;
        if (i + 1 < i1) {
            int sn = __ldg(&g_csrc[i + 1]);
            w_next  = __ldg(&g_w[(i + 1) * 4 + head]);
            hv_next = *(const float4*)&Hm[sn * F + lane * 4];
        }
        sw += w;
        acc.x = fmaf(w, hv.x, acc.x);
        acc.y = fmaf(w, hv.y, acc.y);
        acc.z = fmaf(w, hv.z, acc.z);
        acc.w = fmaf(w, hv.w, acc.w);
    }

    float inv = 1.0f / (sw + 1e-16f);
    float4 b4 = *(const float4*)&bias[lane * 4];
    float4 o;
    o.x = acc.x * inv + b4.x;
    o.y = acc.y * inv + b4.y;
    o.z = acc.z * inv + b4.z;
    o.w = acc.w * inv + b4.w;
    if (do_elu) {
        o.x = o.x > 0.f ? o.x : expm1f(o.x);
        o.y = o.y > 0.f ? o.y : expm1f(o.y);
        o.z = o.z > 0.f ? o.z : expm1f(o.z);
        o.w = o.w > 0.f ? o.w : expm1f(o.w);
    }
    *(float4*)&O[d * F + lane * 4] = o;
}

// ---------------- pooling + final linear (one block per graph, 512 threads) ----------------
__global__ void pool_final_k(const float* __restrict__ B,
                             const int* __restrict__ batch,
                             const float* __restrict__ lw,
                             const float* __restrict__ lb,
                             float* __restrict__ out, int N) {
    int g    = blockIdx.x;
    int tid  = threadIdx.x;       // 0..511
    int c    = tid & 127;         // feature
    int part = tid >> 7;          // 0..3

    int lo = 0, hi = N;
    while (lo < hi) { int mid = (lo + hi) >> 1; if (__ldg(&batch[mid]) < g) lo = mid + 1; else hi = mid; }
    int start = lo;
    hi = N;
    while (lo < hi) { int mid = (lo + hi) >> 1; if (__ldg(&batch[mid]) < g + 1) lo = mid + 1; else hi = mid; }
    int end = lo;

    float sum = 0.f, mx = -INFINITY;
    for (int n = start + part; n < end; n += 4) {
        float v = __ldg(&B[n * F + c]);
        sum += v; mx = fmaxf(mx, v);
    }

    __shared__ float s_sum[512];
    __shared__ float s_max[512];
    s_sum[tid] = sum; s_max[tid] = mx;
    __syncthreads();
    if (part == 0) {
        sum = s_sum[c] + s_sum[c + 128] + s_sum[c + 256] + s_sum[c + 384];
        mx  = fmaxf(fmaxf(s_max[c], s_max[c + 128]), fmaxf(s_max[c + 256], s_max[c + 384]));
        float cnt = fmaxf((float)(end - start), 1.0f);
        if (isinf(mx)) mx = 0.f;
        s_sum[c] = (sum / cnt + mx) * __ldg(&lw[c]);
    }
    __syncthreads();
#pragma unroll
    for (int o = 64; o; o >>= 1) {
        if (tid < o) s_sum[tid] += s_sum[tid + o];
        __syncthreads();
    }
    if (tid == 0) out[g] = s_sum[0] + __ldg(&lb[0]);
}

// ---------------- launcher ----------------
extern "C" void kernel_launch(void* const* d_in, const int* in_sizes, int n_in,
                              void* d_out, int out_size) {
    const float* x     = (const float*)d_in[0];
    const int*   ei    = (const int*)d_in[1];
    const int*   batch = (const int*)d_in[2];
    const float* W1    = (const float*)d_in[3];
    const float* as1   = (const float*)d_in[4];
    const float* ad1   = (const float*)d_in[5];
    const float* b1    = (const float*)d_in[6];
    const float* W2    = (const float*)d_in[7];
    const float* as2   = (const float*)d_in[8];
    const float* ad2   = (const float*)d_in[9];
    const float* b2    = (const float*)d_in[10];
    const float* lw    = (const float*)d_in[11];
    const float* lb    = (const float*)d_in[12];

    int N  = in_sizes[0] / F;
    int E  = in_sizes[1] / 2;
    int Et = E + N;

    float *hptr, *bptr;
    cudaGetSymbolAddress((void**)&hptr, g_h);
    cudaGetSymbolAddress((void**)&bptr, g_buf);

    size_t smem = (size_t)(F * XPAD2) * sizeof(float);
    cudaFuncSetAttribute(gemm_k, cudaFuncAttributeMaxDynamicSharedMemorySize, (int)smem);

    int gemm_blocks      = (N + 127) / 128;
    int node_warp_blocks = (N * 32 + 255) / 256;
    int edge_blocks      = (Et + 255) / 256;

    // ---- CSR build ----
    count_k<<<edge_blocks, 256>>>(ei, E, N);
    scan_k<<<1, 1024>>>(N);
    scatter_k<<<edge_blocks, 256>>>(ei, E, N);

    // ---- layer 1 ----
    gemm_k<<<gemm_blocks, 256, smem>>>(x, W1, hptr, as1, ad1, N);   // 4th -> ncu
    wk_k<<<edge_blocks, 256>>>(Et);
    aggr_k<<<node_warp_blocks, 256>>>(hptr, bptr, b1, N, 1);

    // ---- layer 2 ----
    gemm_k<<<gemm_blocks, 256, smem>>>(bptr, W2, hptr, as2, ad2, N);
    wk_k<<<edge_blocks, 256>>>(Et);
    aggr_k<<<node_warp_blocks, 256>>>(hptr, bptr, b2, N, 0);

    // ---- pooling + final linear ----
    pool_final_k<<<GMAX, 512>>>(bptr, batch, lw, lb, (float*)d_out, N);
}

// round 14
// speedup vs baseline: 2.4368x; 1.0815x over previous
#include <cuda_runtime.h>
#include <math.h>

#define F      128
#define HEADS  4
#define NMAX   50000
#define GMAX   64
#define EMAX   860000
#define XPAD   68

// ---------------- device scratch ----------------
__device__ __align__(16) float g_h   [NMAX * F];
__device__ __align__(16) float g_buf [NMAX * F];
__device__ __align__(16) float g_as  [NMAX * HEADS];
__device__ __align__(16) float g_ad  [NMAX * HEADS];
__device__ __align__(16) float g_w   [EMAX * HEADS];
__device__ __align__(16) int  g_deg [NMAX];            // zero-init; scan_k restores zeros
__device__             int   g_rowptr[NMAX + 1];
__device__             int   g_wpos[NMAX];
__device__             int   g_csrc[EMAX];
__device__             int   g_cdst[EMAX];

__device__ __forceinline__ unsigned long long pack_dup(float a) {
    unsigned long long r;
    asm("mov.b64 %0, {%1, %1};" : "=l"(r) : "f"(a));
    return r;
}
__device__ __forceinline__ void fma_f32x2(unsigned long long& d,
                                          unsigned long long a,
                                          unsigned long long b) {
    asm("fma.rn.f32x2 %0, %1, %2, %0;" : "+l"(d) : "l"(a), "l"(b));
}
__device__ __forceinline__ void unpack2(unsigned long long v, float& lo, float& hi) {
    asm("mov.b64 {%0, %1}, %2;" : "=f"(lo), "=f"(hi) : "l"(v));
}

// ---------------- GEMM (f32x2) + fused alpha: 64-row tile ----------------
__global__ void __launch_bounds__(256, 3)
gemm_k(const float* __restrict__ X, const float* __restrict__ W,
       float* __restrict__ O,
       const float* __restrict__ asr, const float* __restrict__ adt,
       int N) {
    extern __shared__ float xs[];          // [128][XPAD] transposed: xs[k][row]

    const int tid  = threadIdx.x;
    const int row0 = blockIdx.x * 64;

    const float4* X4 = (const float4*)X;
#pragma unroll
    for (int i = 0; i < 8; i++) {
        int idx = tid + i * 256;
        int r = idx >> 5, kq = idx & 31;
        float4 v = make_float4(0.f, 0.f, 0.f, 0.f);
        int gr = row0 + r;
        if (gr < N) v = X4[gr * 32 + kq];
        xs[(4 * kq + 0) * XPAD + r] = v.x;
        xs[(4 * kq + 1) * XPAD + r] = v.y;
        xs[(4 * kq + 2) * XPAD + r] = v.z;
        xs[(4 * kq + 3) * XPAD + r] = v.w;
    }
    __syncthreads();

    const int ty = tid >> 4, tx = tid & 15;   // 4 rows, 8 cols per thread
    unsigned long long acc2[4][4];            // [row][colpair] f32x2
#pragma unroll
    for (int i = 0; i < 4; i++)
#pragma unroll
        for (int j = 0; j < 4; j++) acc2[i][j] = 0ull;

    const ulonglong2* Wp = (const ulonglong2*)W;   // W row: 128 floats = 32 ulonglong2

#pragma unroll 4
    for (int k = 0; k < F; k++) {
        float4 x4 = *(const float4*)&xs[k * XPAD + ty * 4];
        unsigned long long xd[4];
        xd[0] = pack_dup(x4.x);
        xd[1] = pack_dup(x4.y);
        xd[2] = pack_dup(x4.z);
        xd[3] = pack_dup(x4.w);
        // W[k][tx*8 .. tx*8+7] as 4 f32x2 pairs  (row stride = 32 ulonglong2)
        ulonglong2 wa = __ldg(&Wp[k * 32 + tx * 2]);
        ulonglong2 wb = __ldg(&Wp[k * 32 + tx * 2 + 1]);
        unsigned long long wp[4] = {wa.x, wa.y, wb.x, wb.y};
#pragma unroll
        for (int i = 0; i < 4; i++) {
            fma_f32x2(acc2[i][0], xd[i], wp[0]);
            fma_f32x2(acc2[i][1], xd[i], wp[1]);
            fma_f32x2(acc2[i][2], xd[i], wp[2]);
            fma_f32x2(acc2[i][3], xd[i], wp[3]);
        }
    }

    // unpack to scalar accs for epilogue
    float acc[4][8];
#pragma unroll
    for (int i = 0; i < 4; i++)
#pragma unroll
        for (int j = 0; j < 4; j++)
            unpack2(acc2[i][j], acc[i][2 * j], acc[i][2 * j + 1]);

    float4 a0 = *(const float4*)&asr[tx * 8];
    float4 a1 = *(const float4*)&asr[tx * 8 + 4];
    float4 d0 = *(const float4*)&adt[tx * 8];
    float4 d1 = *(const float4*)&adt[tx * 8 + 4];
    float av[8] = {a0.x, a0.y, a0.z, a0.w, a1.x, a1.y, a1.z, a1.w};
    float dv[8] = {d0.x, d0.y, d0.z, d0.w, d1.x, d1.y, d1.z, d1.w};

    const int lane = tid & 31;
    const int head = (lane >> 2) & 3;

#pragma unroll
    for (int i = 0; i < 4; i++) {
        int gr = row0 + ty * 4 + i;
        float ps = 0.f, pd = 0.f;
#pragma unroll
        for (int j = 0; j < 8; j++) {
            ps = fmaf(acc[i][j], av[j], ps);
            pd = fmaf(acc[i][j], dv[j], pd);
        }
        ps += __shfl_down_sync(0xffffffffu, ps, 1, 4);
        ps += __shfl_down_sync(0xffffffffu, ps, 2, 4);
        pd += __shfl_down_sync(0xffffffffu, pd, 1, 4);
        pd += __shfl_down_sync(0xffffffffu, pd, 2, 4);
        if (gr < N) {
            if ((lane & 3) == 0) {
                g_as[gr * 4 + head] = ps;
                g_ad[gr * 4 + head] = pd;
            }
            *(float4*)&O[gr * F + tx * 8]     = make_float4(acc[i][0], acc[i][1], acc[i][2], acc[i][3]);
            *(float4*)&O[gr * F + tx * 8 + 4] = make_float4(acc[i][4], acc[i][5], acc[i][6], acc[i][7]);
        }
    }
}

// ---------------- CSR build ----------------
__global__ void count_k(const int* __restrict__ ei, int E, int N) {
    int i = blockIdx.x * blockDim.x + threadIdx.x;
    int Et = E + N;
    if (i >= Et) return;
    int dst = (i < E) ? __ldg(&ei[E + i]) : (i - E);
    atomicAdd(&g_deg[dst], 1);
}

__global__ void scan_k(int N) {
    __shared__ int warpsum[32];
    __shared__ int carry_s;
    int tid = threadIdx.x, lane = tid & 31, wid = tid >> 5;
    if (tid == 0) carry_s = 0;
    __syncthreads();
    for (int base = 0; base < N; base += 4096) {
        int i = base + tid * 4;
        int4 v = make_int4(0, 0, 0, 0);
        bool full = (i + 3 < N);
        if (full) v = *(const int4*)&g_deg[i];
        else if (i < N) {
            v.x = g_deg[i];
            if (i + 1 < N) v.y = g_deg[i + 1];
            if (i + 2 < N) v.z = g_deg[i + 2];
        }
        int t1 = v.x + v.y, t2 = t1 + v.z, t3 = t2 + v.w;
        int x = t3;
#pragma unroll
        for (int o = 1; o < 32; o <<= 1) {
            int t = __shfl_up_sync(0xffffffffu, x, o);
            if (lane >= o) x += t;
        }
        if (lane == 31) warpsum[wid] = x;
        __syncthreads();
        if (wid == 0) {
            int s = warpsum[lane];
#pragma unroll
            for (int o = 1; o < 32; o <<= 1) {
                int t = __shfl_up_sync(0xffffffffu, s, o);
                if (lane >= o) s += t;
            }
            warpsum[lane] = s;
        }
        __syncthreads();
        int c    = carry_s;
        int pref = (wid > 0) ? warpsum[wid - 1] : 0;
        int e0 = c + pref + (x - t3);
        if (full) {
            g_rowptr[i] = e0;       g_wpos[i]     = e0;
            g_rowptr[i+1] = e0+v.x; g_wpos[i+1]   = e0+v.x;
            g_rowptr[i+2] = e0+t1;  g_wpos[i+2]   = e0+t1;
            g_rowptr[i+3] = e0+t2;  g_wpos[i+3]   = e0+t2;
            *(int4*)&g_deg[i] = make_int4(0, 0, 0, 0);
        } else if (i < N) {
            g_rowptr[i] = e0; g_wpos[i] = e0; g_deg[i] = 0;
            if (i+1 < N) { g_rowptr[i+1] = e0+v.x; g_wpos[i+1] = e0+v.x; g_deg[i+1] = 0; }
            if (i+2 < N) { g_rowptr[i+2] = e0+t1;  g_wpos[i+2] = e0+t1;  g_deg[i+2] = 0; }
        }
        __syncthreads();
        if (tid == 1023) carry_s = c + pref + x;
        __syncthreads();
    }
    if (threadIdx.x == 0) g_rowptr[N] = carry_s;
}

__global__ void scatter_k(const int* __restrict__ ei, int E, int N) {
    int i = blockIdx.x * blockDim.x + threadIdx.x;
    int Et = E + N;
    if (i >= Et) return;
    int src, dst;
    if (i < E) { src = ei[i]; dst = ei[E + i]; }
    else       { src = dst = i - E; }
    int pos = atomicAdd(&g_wpos[dst], 1);
    g_csrc[pos] = src;
    g_cdst[pos] = dst;
}

// ---------------- edge weight precompute ----------------
__global__ void wk_k(int Et) {
    int i = blockIdx.x * blockDim.x + threadIdx.x;
    if (i >= Et) return;
    int s = g_csrc[i];
    int d = g_cdst[i];
    float4 a = *(const float4*)&g_as[s * 4];
    float4 b = *(const float4*)&g_ad[d * 4];
    float4 w;
    float e;
    e = a.x + b.x; e = e > 0.f ? e : 0.2f * e; w.x = __expf(e);
    e = a.y + b.y; e = e > 0.f ? e : 0.2f * e; w.y = __expf(e);
    e = a.z + b.z; e = e > 0.f ? e : 0.2f * e; w.z = __expf(e);
    e = a.w + b.w; e = e > 0.f ? e : 0.2f * e; w.w = __expf(e);
    *(float4*)&g_w[i * 4] = w;
}

// ---------------- aggregation + bias (+ELU), warp per dst ----------------
__global__ void __launch_bounds__(256)
aggr_k(const float* __restrict__ Hm,
       float* __restrict__ O,
       const float* __restrict__ bias,
       int N, int do_elu) {
    int d    = (blockIdx.x * blockDim.x + threadIdx.x) >> 5;
    int lane = threadIdx.x & 31;
    if (d >= N) return;
    int head = lane >> 3;

    int i0 = g_rowptr[d];
    int i1 = g_rowptr[d + 1];

    float4 acc = make_float4(0.f, 0.f, 0.f, 0.f);
    float sw = 0.f;

    float  w_next  = 0.f;
    float4 hv_next = make_float4(0.f, 0.f, 0.f, 0.f);
    if (i0 < i1) {
        int sn = __ldg(&g_csrc[i0]);
        w_next  = __ldg(&g_w[i0 * 4 + head]);
        hv_next = *(const float4*)&Hm[sn * F + lane * 4];
    }

    for (int i = i0; i < i1; i++) {
        float  w  = w_next;
        float4 hv = hv_next;
        if (i + 1 < i1) {
            int sn = __ldg(&g_csrc[i + 1]);
            w_next  = __ldg(&g_w[(i + 1) * 4 + head]);
            hv_next = *(const float4*)&Hm[sn * F + lane * 4];
        }
        sw += w;
        acc.x = fmaf(w, hv.x, acc.x);
        acc.y = fmaf(w, hv.y, acc.y);
        acc.z = fmaf(w, hv.z, acc.z);
        acc.w = fmaf(w, hv.w, acc.w);
    }

    float inv = 1.0f / (sw + 1e-16f);
    float4 b4 = *(const float4*)&bias[lane * 4];
    float4 o;
    o.x = acc.x * inv + b4.x;
    o.y = acc.y * inv + b4.y;
    o.z = acc.z * inv + b4.z;
    o.w = acc.w * inv + b4.w;
    if (do_elu) {
        o.x = o.x > 0.f ? o.x : expm1f(o.x);
        o.y = o.y > 0.f ? o.y : expm1f(o.y);
        o.z = o.z > 0.f ? o.z : expm1f(o.z);
        o.w = o.w > 0.f ? o.w : expm1f(o.w);
    }
    *(float4*)&O[d * F + lane * 4] = o;
}

// ---------------- pooling + final linear ----------------
__global__ void pool_final_k(const float* __restrict__ B,
                             const int* __restrict__ batch,
                             const float* __restrict__ lw,
                             const float* __restrict__ lb,
                             float* __restrict__ out, int N) {
    int g    = blockIdx.x;
    int tid  = threadIdx.x;       // 0..511
    int c    = tid & 127;
    int part = tid >> 7;

    int lo = 0, hi = N;
    while (lo < hi) { int mid = (lo + hi) >> 1; if (__ldg(&batch[mid]) < g) lo = mid + 1; else hi = mid; }
    int start = lo;
    hi = N;
    while (lo < hi) { int mid = (lo + hi) >> 1; if (__ldg(&batch[mid]) < g + 1) lo = mid + 1; else hi = mid; }
    int end = lo;

    float sum = 0.f, mx = -INFINITY;
    for (int n = start + part; n < end; n += 4) {
        float v = __ldg(&B[n * F + c]);
        sum += v; mx = fmaxf(mx, v);
    }

    __shared__ float s_sum[512];
    __shared__ float s_max[512];
    s_sum[tid] = sum; s_max[tid] = mx;
    __syncthreads();
    if (part == 0) {
        sum = s_sum[c] + s_sum[c + 128] + s_sum[c + 256] + s_sum[c + 384];
        mx  = fmaxf(fmaxf(s_max[c], s_max[c + 128]), fmaxf(s_max[c + 256], s_max[c + 384]));
        float cnt = fmaxf((float)(end - start), 1.0f);
        if (isinf(mx)) mx = 0.f;
        s_sum[c] = (sum / cnt + mx) * __ldg(&lw[c]);
    }
    __syncthreads();
#pragma unroll
    for (int o = 64; o; o >>= 1) {
        if (tid < o) s_sum[tid] += s_sum[tid + o];
        __syncthreads();
    }
    if (tid == 0) out[g] = s_sum[0] + __ldg(&lb[0]);
}

// ---------------- launcher ----------------
extern "C" void kernel_launch(void* const* d_in, const int* in_sizes, int n_in,
                              void* d_out, int out_size) {
    const float* x     = (const float*)d_in[0];
    const int*   ei    = (const int*)d_in[1];
    const int*   batch = (const int*)d_in[2];
    const float* W1    = (const float*)d_in[3];
    const float* as1   = (const float*)d_in[4];
    const float* ad1   = (const float*)d_in[5];
    const float* b1    = (const float*)d_in[6];
    const float* W2    = (const float*)d_in[7];
    const float* as2   = (const float*)d_in[8];
    const float* ad2   = (const float*)d_in[9];
    const float* b2    = (const float*)d_in[10];
    const float* lw    = (const float*)d_in[11];
    const float* lb    = (const float*)d_in[12];

    int N  = in_sizes[0] / F;
    int E  = in_sizes[1] / 2;
    int Et = E + N;

    float *hptr, *bptr;
    cudaGetSymbolAddress((void**)&hptr, g_h);
    cudaGetSymbolAddress((void**)&bptr, g_buf);

    size_t smem = (size_t)(F * XPAD) * sizeof(float);
    cudaFuncSetAttribute(gemm_k, cudaFuncAttributeMaxDynamicSharedMemorySize, (int)smem);

    int gemm_blocks      = (N + 63) / 64;
    int node_warp_blocks = (N * 32 + 255) / 256;
    int edge_blocks      = (Et + 255) / 256;

    // ---- CSR build ----
    count_k<<<edge_blocks, 256>>>(ei, E, N);
    scan_k<<<1, 1024>>>(N);
    scatter_k<<<edge_blocks, 256>>>(ei, E, N);

    // ---- layer 1 ----
    gemm_k<<<gemm_blocks, 256, smem>>>(x, W1, hptr, as1, ad1, N);   // 4th -> ncu
    wk_k<<<edge_blocks, 256>>>(Et);
    aggr_k<<<node_warp_blocks, 256>>>(hptr, bptr, b1, N, 1);

    // ---- layer 2 ----
    gemm_k<<<gemm_blocks, 256, smem>>>(bptr, W2, hptr, as2, ad2, N);
    wk_k<<<edge_blocks, 256>>>(Et);
    aggr_k<<<node_warp_blocks, 256>>>(hptr, bptr, b2, N, 0);

    // ---- pooling + final linear ----
    pool_final_k<<<GMAX, 512>>>(bptr, batch, lw, lb, (float*)d_out, N);
}